// round 2
// baseline (speedup 1.0000x reference)
#include <cuda_runtime.h>
#include <cmath>

// ---------------------------------------------------------------------------
// CTLNN persistent kernel.
// 128 CTAs (one per SM), 256 threads each. Column-partitioned weights live in
// SMEM; activations are exchanged through L2 (__ldcg) with a custom atomic
// grid barrier. Each CTA owns H-columns [4*bid, 4*bid+4) of every H-sized
// quantity, plus the paired g/core columns of the 2H-wide input mapper.
// ---------------------------------------------------------------------------

namespace {
constexpr int Bz   = 64;
constexpr int Tt   = 1024;
constexpr int DIN  = 256;
constexpr int Hh   = 512;
constexpr int NCTA = 128;
constexpr int NTHR = 256;
constexpr float DTc = 0.01f;
constexpr float EPSc = 1e-5f;

// SMEM layout (float offsets)
constexpr int OFF_WM    = 0;           // 8*768  : [c8][k], c8<4 -> g cols, c8>=4 -> core cols
constexpr int OFF_WT    = 6144;        // 4*512  : [c][k]
constexpr int OFF_WF1   = 8192;        // 4*512
constexpr int OFF_WF2   = 10240;       // 4*512
constexpr int OFF_STAGE = 12288;       // 64 rows * 256 floats (swizzled, float4 granules)
constexpr int OFF_BMG   = 28672;
constexpr int OFF_BMC   = 28676;
constexpr int OFF_BT    = 28680;
constexpr int OFF_BF1   = 28684;
constexpr int OFF_BF2   = 28688;
constexpr int OFF_GAM   = 28692;
constexpr int OFF_BET   = 28696;
constexpr int OFF_REDS  = 28704;       // 64
constexpr int OFF_REDQ  = 28768;       // 64
constexpr int SMEM_FLOATS = 28832;     // 115328 bytes
}

// Cross-CTA communication buffers (device globals: no allocations allowed).
__device__ unsigned g_bar;
__device__ float g_rs[2 * 64];
__device__ float g_rq[2 * 64];
__device__ float g_z[Bz * Hh];
__device__ float g_core[Bz * Hh];
__device__ float g_a1[Bz * Hh];

__global__ void ctlnn_reset() {
    if (threadIdx.x == 0) g_bar = 0u;
    if (threadIdx.x < 128) {
        g_rs[threadIdx.x] = 0.f;
        g_rq[threadIdx.x] = 0.f;
    }
}

// Grid-wide barrier: monotonically increasing counter, one arrive per CTA.
__device__ __forceinline__ void grid_bar(unsigned target) {
    __threadfence();
    __syncthreads();
    if (threadIdx.x == 0) {
        atomicAdd(&g_bar, 1u);
        volatile unsigned* p = &g_bar;
        while (*p < target) { }
    }
    __syncthreads();
}

__global__ void __launch_bounds__(NTHR, 1)
ctlnn_main(const float* __restrict__ x,
           const float* __restrict__ Wm,  const float* __restrict__ bm,
           const float* __restrict__ Wf1, const float* __restrict__ bf1,
           const float* __restrict__ Wf2, const float* __restrict__ bf2,
           const float* __restrict__ Wt,  const float* __restrict__ bt,
           const float* __restrict__ gamma, const float* __restrict__ beta,
           float* __restrict__ out) {
    extern __shared__ __align__(16) float sm[];
    const int tid = threadIdx.x;
    const int bid = blockIdx.x;

    // ---- load this CTA's weight slices into SMEM (once per launch) ----
    for (int idx = tid; idx < 8 * 768; idx += NTHR) {
        int c8 = idx / 768;
        int k  = idx - c8 * 768;
        int srccol = (c8 < 4) ? (bid * 4 + c8) : (512 + bid * 4 + (c8 - 4));
        sm[OFF_WM + idx] = Wm[k * 1024 + srccol];
    }
    for (int idx = tid; idx < 4 * 512; idx += NTHR) {
        int c4 = idx >> 9;
        int k  = idx & 511;
        int col0 = bid * 4 + c4;
        sm[OFF_WT  + idx] = Wt [k * 512 + col0];
        sm[OFF_WF1 + idx] = Wf1[k * 512 + col0];
        sm[OFF_WF2 + idx] = Wf2[k * 512 + col0];
    }
    if (tid < 4) {
        int col0 = bid * 4 + tid;
        sm[OFF_BMG + tid] = bm[col0];
        sm[OFF_BMC + tid] = bm[512 + col0];
        sm[OFF_BT  + tid] = bt[col0];
        sm[OFF_BF1 + tid] = bf1[col0];
        sm[OFF_BF2 + tid] = bf2[col0];
        sm[OFF_GAM + tid] = gamma[col0];
        sm[OFF_BET + tid] = beta[col0];
    }
    __syncthreads();

    float4* stage4 = reinterpret_cast<float4*>(sm + OFF_STAGE);
    const float4* Wm4  = reinterpret_cast<const float4*>(sm + OFF_WM);
    const float4* Wt4  = reinterpret_cast<const float4*>(sm + OFF_WT);
    const float4* Wf14 = reinterpret_cast<const float4*>(sm + OFF_WF1);
    const float4* Wf24 = reinterpret_cast<const float4*>(sm + OFF_WF2);

    const int r   = tid & 63;       // batch row this thread computes
    const int cc  = tid >> 6;       // local column 0..3
    const int col = bid * 4 + cc;   // global H-column
    const int sw  = r & 7;          // swizzle key for reads
    const int rs0 = tid >> 6;       // staging: row phase
    const int kk  = tid & 63;       // staging: granule index

    unsigned bar_t = 0;

    for (int t = 0; t < Tt; ++t) {
        const int par = t & 1;

        // =========== PHASE A: mapped = [x_t, h] @ Wm; z, core ===========
        float4 aG = make_float4(0.f, 0.f, 0.f, 0.f);
        float4 aC = make_float4(0.f, 0.f, 0.f, 0.f);
        for (int chunk = 0; chunk < 3; ++chunk) {
            __syncthreads();
            #pragma unroll
            for (int i = 0; i < 16; ++i) {
                int rs = rs0 + i * 4;
                float4 v;
                if (chunk == 0) {
                    v = __ldg(reinterpret_cast<const float4*>(
                            x + (size_t)rs * (Tt * DIN) + t * DIN + kk * 4));
                } else if (t == 0) {
                    v = make_float4(0.f, 0.f, 0.f, 0.f);
                } else {
                    v = __ldcg(reinterpret_cast<const float4*>(
                            out + (size_t)rs * (Tt * Hh) + (t - 1) * Hh
                                + (chunk - 1) * 256 + kk * 4));
                }
                stage4[rs * 64 + (kk ^ (rs & 7))] = v;
            }
            __syncthreads();
            const float4* sp = stage4 + r * 64;
            const float4* wg = Wm4 + cc * 192 + chunk * 64;
            const float4* wc = Wm4 + (cc + 4) * 192 + chunk * 64;
            #pragma unroll 8
            for (int k4 = 0; k4 < 64; ++k4) {
                float4 a = sp[k4 ^ sw];
                float4 g = wg[k4];
                float4 c = wc[k4];
                aG.x += a.x * g.x; aG.y += a.y * g.y;
                aG.z += a.z * g.z; aG.w += a.w * g.w;
                aC.x += a.x * c.x; aC.y += a.y * c.y;
                aC.z += a.z * c.z; aC.w += a.w * c.w;
            }
        }
        {
            float gv = (aG.x + aG.y) + (aG.z + aG.w) + sm[OFF_BMG + cc];
            float cv = (aC.x + aC.y) + (aC.z + aC.w) + sm[OFF_BMC + cc];
            float sg = 1.f / (1.f + expf(-gv));
            float z  = sg * tanhf(cv);
            g_z[r * Hh + col]    = z;
            g_core[r * Hh + col] = cv;
        }
        bar_t += NCTA; grid_bar(bar_t);

        // =========== PHASE B: tau = softplus(core @ Wt + bt) ============
        float4 aT = make_float4(0.f, 0.f, 0.f, 0.f);
        for (int chunk = 0; chunk < 2; ++chunk) {
            __syncthreads();
            #pragma unroll
            for (int i = 0; i < 16; ++i) {
                int rs = rs0 + i * 4;
                float4 v = __ldcg(reinterpret_cast<const float4*>(
                        g_core + rs * Hh + chunk * 256 + kk * 4));
                stage4[rs * 64 + (kk ^ (rs & 7))] = v;
            }
            __syncthreads();
            const float4* sp = stage4 + r * 64;
            const float4* w  = Wt4 + cc * 128 + chunk * 64;
            #pragma unroll 8
            for (int k4 = 0; k4 < 64; ++k4) {
                float4 a = sp[k4 ^ sw];
                float4 ww = w[k4];
                aT.x += a.x * ww.x; aT.y += a.y * ww.y;
                aT.z += a.z * ww.z; aT.w += a.w * ww.w;
            }
        }
        float dtTau;
        {
            float tl = (aT.x + aT.y) + (aT.z + aT.w) + sm[OFF_BT + cc];
            float spv = (tl > 20.f) ? tl : log1pf(expf(tl));
            dtTau = DTc / (spv + 1e-6f);
        }

        // =========== PHASE C: a1 = silu(z @ Wf1 + bf1) ==================
        float4 aF = make_float4(0.f, 0.f, 0.f, 0.f);
        for (int chunk = 0; chunk < 2; ++chunk) {
            __syncthreads();
            #pragma unroll
            for (int i = 0; i < 16; ++i) {
                int rs = rs0 + i * 4;
                float4 v = __ldcg(reinterpret_cast<const float4*>(
                        g_z + rs * Hh + chunk * 256 + kk * 4));
                stage4[rs * 64 + (kk ^ (rs & 7))] = v;
            }
            __syncthreads();
            const float4* sp = stage4 + r * 64;
            const float4* w  = Wf14 + cc * 128 + chunk * 64;
            #pragma unroll 8
            for (int k4 = 0; k4 < 64; ++k4) {
                float4 a = sp[k4 ^ sw];
                float4 ww = w[k4];
                aF.x += a.x * ww.x; aF.y += a.y * ww.y;
                aF.z += a.z * ww.z; aF.w += a.w * ww.w;
            }
        }
        {
            float f1 = (aF.x + aF.y) + (aF.z + aF.w) + sm[OFF_BF1 + cc];
            float a1 = f1 / (1.f + expf(-f1));
            g_a1[r * Hh + col] = a1;
        }
        bar_t += NCTA; grid_bar(bar_t);

        // =========== PHASE D: f = a1 @ Wf2 + bf2; v = h + dt/tau*f ======
        float4 aO = make_float4(0.f, 0.f, 0.f, 0.f);
        for (int chunk = 0; chunk < 2; ++chunk) {
            __syncthreads();
            #pragma unroll
            for (int i = 0; i < 16; ++i) {
                int rs = rs0 + i * 4;
                float4 v = __ldcg(reinterpret_cast<const float4*>(
                        g_a1 + rs * Hh + chunk * 256 + kk * 4));
                stage4[rs * 64 + (kk ^ (rs & 7))] = v;
            }
            __syncthreads();
            const float4* sp = stage4 + r * 64;
            const float4* w  = Wf24 + cc * 128 + chunk * 64;
            #pragma unroll 8
            for (int k4 = 0; k4 < 64; ++k4) {
                float4 a = sp[k4 ^ sw];
                float4 ww = w[k4];
                aO.x += a.x * ww.x; aO.y += a.y * ww.y;
                aO.z += a.z * ww.z; aO.w += a.w * ww.w;
            }
        }
        float v;
        {
            float f = (aO.x + aO.y) + (aO.z + aO.w) + sm[OFF_BF2 + cc];
            float hp = (t == 0) ? 0.f
                     : __ldcg(out + (size_t)r * (Tt * Hh) + (t - 1) * Hh + col);
            v = hp + dtTau * f;
        }
        // cross-CTA row sum / sumsq reduction (SMEM first, then L2 atomics)
        if (tid < 64) { sm[OFF_REDS + tid] = 0.f; sm[OFF_REDQ + tid] = 0.f; }
        __syncthreads();
        atomicAdd(&sm[OFF_REDS + r], v);
        atomicAdd(&sm[OFF_REDQ + r], v * v);
        __syncthreads();
        if (tid < 64) {
            atomicAdd(&g_rs[par * 64 + tid], sm[OFF_REDS + tid]);
            atomicAdd(&g_rq[par * 64 + tid], sm[OFF_REDQ + tid]);
        }
        bar_t += NCTA; grid_bar(bar_t);

        // =========== PHASE E: LayerNorm, write h_new to out =============
        {
            float s = __ldcg(&g_rs[par * 64 + r]);
            float q = __ldcg(&g_rq[par * 64 + r]);
            float mu  = s * (1.f / 512.f);
            float var = q * (1.f / 512.f) - mu * mu;
            float rstd = rsqrtf(var + EPSc);
            float hn = (v - mu) * rstd * sm[OFF_GAM + cc] + sm[OFF_BET + cc];
            out[(size_t)r * (Tt * Hh) + t * Hh + col] = hn;
        }
        // zero the other-parity accumulators for step t+1
        if (tid < 64) {
            g_rs[(par ^ 1) * 64 + tid] = 0.f;
            g_rq[(par ^ 1) * 64 + tid] = 0.f;
        }
        bar_t += NCTA; grid_bar(bar_t);
    }
}

extern "C" void kernel_launch(void* const* d_in, const int* in_sizes, int n_in,
                              void* d_out, int out_size) {
    const float* x     = (const float*)d_in[0];
    const float* Wm    = (const float*)d_in[1];
    const float* bm    = (const float*)d_in[2];
    const float* Wf1   = (const float*)d_in[3];
    const float* bf1   = (const float*)d_in[4];
    const float* Wf2   = (const float*)d_in[5];
    const float* bf2   = (const float*)d_in[6];
    const float* Wt    = (const float*)d_in[7];
    const float* bt    = (const float*)d_in[8];
    const float* gamma = (const float*)d_in[9];
    const float* beta  = (const float*)d_in[10];
    float* out = (float*)d_out;

    cudaFuncSetAttribute(ctlnn_main, cudaFuncAttributeMaxDynamicSharedMemorySize,
                         SMEM_FLOATS * sizeof(float));

    ctlnn_reset<<<1, 128>>>();
    ctlnn_main<<<NCTA, NTHR, SMEM_FLOATS * sizeof(float)>>>(
        x, Wm, bm, Wf1, bf1, Wf2, bf2, Wt, bt, gamma, beta, out);
}

// round 3
// speedup vs baseline: 1.6134x; 1.6134x over previous
#include <cuda_runtime.h>
#include <cmath>

// ---------------------------------------------------------------------------
// CTLNN persistent kernel, round 3.
// 128 CTAs x 256 threads. Column-partitioned weights in SMEM. Activations
// exchanged through L2 with cp.async double-buffered staging and FFMA2
// (fma.rn.f32x2) inner loops. 4 grid barriers per step.
// ---------------------------------------------------------------------------

namespace {
constexpr int Bz   = 64;
constexpr int Tt   = 1024;
constexpr int DIN  = 256;
constexpr int Hh   = 512;
constexpr int NCTA = 128;
constexpr int NTHR = 256;
constexpr float DTc  = 0.01f;
constexpr float EPSc = 1e-5f;

// SMEM layout (float offsets)
constexpr int OFF_WM    = 0;        // 8*768: c8<4 -> g cols, c8>=4 -> core cols, [c][k]
constexpr int OFF_WT    = 6144;     // 4*512 [c][k]
constexpr int OFF_WF1   = 8192;
constexpr int OFF_WF2   = 10240;
constexpr int OFF_STAGE = 12288;    // 2 buffers * 64 rows * 256 floats = 32768 floats
constexpr int OFF_B     = 45056;    // bmg[4] bmc[4] bt[4] bf1[4] bf2[4] gam[4] bet[4]
constexpr int OFF_REDS  = 45088;    // 64
constexpr int OFF_REDQ  = 45152;    // 64
constexpr int SMEM_FLOATS = 45216;  // ~180.9 KB
}

// Cross-CTA state (no allocations allowed -> device globals)
__device__ unsigned g_bar;
__device__ float g_rs[128], g_rq[128];
__device__ float g_core[Bz * Hh];
__device__ float g_z[Bz * Hh];
__device__ float g_a1[Bz * Hh];
__device__ float g_h[Bz * Hh];

__global__ void ctlnn_reset() {
    int i = blockIdx.x * blockDim.x + threadIdx.x;
    if (i == 0) g_bar = 0u;
    if (i < 128) { g_rs[i] = 0.f; g_rq[i] = 0.f; }
    for (int k = i; k < Bz * Hh; k += gridDim.x * blockDim.x) g_h[k] = 0.f;
}

// ---- helpers --------------------------------------------------------------
__device__ __forceinline__ void cp16(float4* dst, const float4* src) {
    unsigned s = (unsigned)__cvta_generic_to_shared(dst);
    asm volatile("cp.async.cg.shared.global [%0], [%1], 16;" :: "r"(s), "l"(src));
}
__device__ __forceinline__ void cp_commit() {
    asm volatile("cp.async.commit_group;" ::: "memory");
}
template <int N>
__device__ __forceinline__ void cp_wait() {
    asm volatile("cp.async.wait_group %0;" :: "n"(N) : "memory");
}
__device__ __forceinline__ void fma2(unsigned long long& d,
                                     unsigned long long a, unsigned long long b) {
    asm volatile("fma.rn.f32x2 %0, %1, %2, %3;" : "=l"(d) : "l"(a), "l"(b), "l"(d));
}
__device__ __forceinline__ float hsum(unsigned long long u) {
    float lo, hi;
    asm("mov.b64 {%0,%1}, %2;" : "=f"(lo), "=f"(hi) : "l"(u));
    return lo + hi;
}

// Grid-wide barrier: monotonically increasing counter, one arrive per CTA.
__device__ __forceinline__ void grid_bar(unsigned target) {
    __threadfence();
    __syncthreads();
    if (threadIdx.x == 0) {
        atomicAdd(&g_bar, 1u);
        unsigned v;
        do {
            asm volatile("ld.global.acquire.gpu.u32 %0, [%1];"
                         : "=r"(v) : "l"(&g_bar));
        } while (v < target);
    }
    __syncthreads();
}

// Stage one 64x256-float chunk: row rs gets granule kk at swizzled slot.
__device__ __forceinline__ void stage_issue(float4* __restrict__ dst,
                                            const float* __restrict__ gsrc,
                                            int strideF, int rs0, int kk) {
#pragma unroll
    for (int i = 0; i < 16; ++i) {
        int rs = rs0 + i * 4;
        cp16(dst + rs * 64 + (kk ^ (rs & 7)),
             reinterpret_cast<const float4*>(gsrc + (size_t)rs * strideF) + kk);
    }
    cp_commit();
}

// Dual-output dot (phase A): 64 float4 granules.
__device__ __forceinline__ void dotA(const ulonglong2* __restrict__ sp, int sw,
                                     const ulonglong2* __restrict__ wg,
                                     const ulonglong2* __restrict__ wc,
                                     unsigned long long& g0, unsigned long long& g1,
                                     unsigned long long& c0, unsigned long long& c1) {
#pragma unroll 8
    for (int k = 0; k < 64; ++k) {
        ulonglong2 a = sp[k ^ sw];
        ulonglong2 g = wg[k];
        ulonglong2 c = wc[k];
        fma2(g0, a.x, g.x); fma2(g1, a.y, g.y);
        fma2(c0, a.x, c.x); fma2(c1, a.y, c.y);
    }
}
// Single-output dot (phases B/C/D).
__device__ __forceinline__ void dot1(const ulonglong2* __restrict__ sp, int sw,
                                     const ulonglong2* __restrict__ w,
                                     unsigned long long& d0, unsigned long long& d1) {
#pragma unroll 8
    for (int k = 0; k < 64; ++k) {
        ulonglong2 a = sp[k ^ sw];
        ulonglong2 ww = w[k];
        fma2(d0, a.x, ww.x); fma2(d1, a.y, ww.y);
    }
}

__global__ void __launch_bounds__(NTHR, 1)
ctlnn_main(const float* __restrict__ x,
           const float* __restrict__ Wm,  const float* __restrict__ bm,
           const float* __restrict__ Wf1, const float* __restrict__ bf1,
           const float* __restrict__ Wf2, const float* __restrict__ bf2,
           const float* __restrict__ Wt,  const float* __restrict__ bt,
           const float* __restrict__ gamma, const float* __restrict__ beta,
           float* __restrict__ out) {
    extern __shared__ __align__(16) float sm[];
    const int tid = threadIdx.x;
    const int bid = blockIdx.x;

    // ---- one-time weight slice load ----
    for (int idx = tid; idx < 8 * 768; idx += NTHR) {
        int c8 = idx / 768;
        int k  = idx - c8 * 768;
        int srccol = (c8 < 4) ? (bid * 4 + c8) : (512 + bid * 4 + (c8 - 4));
        sm[OFF_WM + idx] = Wm[k * 1024 + srccol];
    }
    for (int idx = tid; idx < 4 * 512; idx += NTHR) {
        int c4 = idx >> 9;
        int k  = idx & 511;
        int col0 = bid * 4 + c4;
        sm[OFF_WT  + idx] = Wt [k * 512 + col0];
        sm[OFF_WF1 + idx] = Wf1[k * 512 + col0];
        sm[OFF_WF2 + idx] = Wf2[k * 512 + col0];
    }
    if (tid < 4) {
        int col0 = bid * 4 + tid;
        sm[OFF_B +  0 + tid] = bm[col0];
        sm[OFF_B +  4 + tid] = bm[512 + col0];
        sm[OFF_B +  8 + tid] = bt[col0];
        sm[OFF_B + 12 + tid] = bf1[col0];
        sm[OFF_B + 16 + tid] = bf2[col0];
        sm[OFF_B + 20 + tid] = gamma[col0];
        sm[OFF_B + 24 + tid] = beta[col0];
    }
    __syncthreads();

    float4* stA = reinterpret_cast<float4*>(sm + OFF_STAGE);  // buffer 0
    float4* stB = stA + 64 * 64;                              // buffer 1
    const ulonglong2* Wm2  = reinterpret_cast<const ulonglong2*>(sm + OFF_WM);
    const ulonglong2* Wt2  = reinterpret_cast<const ulonglong2*>(sm + OFF_WT);
    const ulonglong2* Wf12 = reinterpret_cast<const ulonglong2*>(sm + OFF_WF1);
    const ulonglong2* Wf22 = reinterpret_cast<const ulonglong2*>(sm + OFF_WF2);

    const int r   = tid & 63;
    const int cc  = tid >> 6;
    const int col = bid * 4 + cc;
    const int sw  = r & 7;
    const int rs0 = tid >> 6;
    const int kk  = tid & 63;

    float hprev = 0.f;
    unsigned bar_t = 0;

    // prefetch x for t=0 into buffer A
    stage_issue(stA, x + 0, Tt * DIN, rs0, kk);

    for (int t = 0; t < Tt; ++t) {
        const int par = t & 1;

        // ================= PHASE A: mapped = [x_t, h] @ Wm =================
        stage_issue(stB, g_h + 0, Hh, rs0, kk);              // h chunk0
        unsigned long long aG0 = 0, aG1 = 0, aC0 = 0, aC1 = 0;
        cp_wait<1>(); __syncthreads();                       // x ready (buf A)
        dotA(reinterpret_cast<const ulonglong2*>(stA + r * 64), sw,
             Wm2 + cc * 192 + 0, Wm2 + (cc + 4) * 192 + 0, aG0, aG1, aC0, aC1);
        __syncthreads();
        stage_issue(stA, g_h + 256, Hh, rs0, kk);            // h chunk1
        cp_wait<1>(); __syncthreads();                       // h chunk0 ready
        dotA(reinterpret_cast<const ulonglong2*>(stB + r * 64), sw,
             Wm2 + cc * 192 + 64, Wm2 + (cc + 4) * 192 + 64, aG0, aG1, aC0, aC1);
        __syncthreads();
        cp_wait<0>(); __syncthreads();                       // h chunk1 ready
        dotA(reinterpret_cast<const ulonglong2*>(stA + r * 64), sw,
             Wm2 + cc * 192 + 128, Wm2 + (cc + 4) * 192 + 128, aG0, aG1, aC0, aC1);
        {
            float gv = hsum(aG0) + hsum(aG1) + sm[OFF_B + 0 + cc];
            float cv = hsum(aC0) + hsum(aC1) + sm[OFF_B + 4 + cc];
            float sg = 1.f / (1.f + expf(-gv));
            g_core[r * Hh + col] = cv;
            g_z[r * Hh + col]    = sg * tanhf(cv);
        }
        bar_t += NCTA; grid_bar(bar_t);

        // ======== PHASE B: tau | PHASE C: a1 = silu(z@Wf1+bf1) =============
        stage_issue(stB, g_core + 0,   Hh, rs0, kk);
        stage_issue(stA, g_core + 256, Hh, rs0, kk);
        unsigned long long t0 = 0, t1 = 0;
        cp_wait<1>(); __syncthreads();                       // core0 ready
        dot1(reinterpret_cast<const ulonglong2*>(stB + r * 64), sw,
             Wt2 + cc * 128 + 0, t0, t1);
        __syncthreads();
        stage_issue(stB, g_z + 0, Hh, rs0, kk);
        cp_wait<1>(); __syncthreads();                       // core1 ready
        dot1(reinterpret_cast<const ulonglong2*>(stA + r * 64), sw,
             Wt2 + cc * 128 + 64, t0, t1);
        __syncthreads();
        stage_issue(stA, g_z + 256, Hh, rs0, kk);
        float dtTau;
        {
            float tl = hsum(t0) + hsum(t1) + sm[OFF_B + 8 + cc];
            float spv = (tl > 20.f) ? tl : log1pf(expf(tl));
            dtTau = DTc / (spv + 1e-6f);
        }
        unsigned long long f0 = 0, f1 = 0;
        cp_wait<1>(); __syncthreads();                       // z0 ready
        dot1(reinterpret_cast<const ulonglong2*>(stB + r * 64), sw,
             Wf12 + cc * 128 + 0, f0, f1);
        __syncthreads();
        cp_wait<0>(); __syncthreads();                       // z1 ready
        dot1(reinterpret_cast<const ulonglong2*>(stA + r * 64), sw,
             Wf12 + cc * 128 + 64, f0, f1);
        {
            float f1v = hsum(f0) + hsum(f1) + sm[OFF_B + 12 + cc];
            g_a1[r * Hh + col] = f1v / (1.f + expf(-f1v));
        }
        bar_t += NCTA; grid_bar(bar_t);

        // ========== PHASE D: f = a1@Wf2 + bf2; v = h + dt/tau * f ==========
        stage_issue(stB, g_a1 + 0,   Hh, rs0, kk);
        stage_issue(stA, g_a1 + 256, Hh, rs0, kk);
        unsigned long long o0 = 0, o1 = 0;
        cp_wait<1>(); __syncthreads();
        dot1(reinterpret_cast<const ulonglong2*>(stB + r * 64), sw,
             Wf22 + cc * 128 + 0, o0, o1);
        __syncthreads();
        cp_wait<0>(); __syncthreads();
        dot1(reinterpret_cast<const ulonglong2*>(stA + r * 64), sw,
             Wf22 + cc * 128 + 64, o0, o1);
        float v;
        {
            float f = hsum(o0) + hsum(o1) + sm[OFF_B + 16 + cc];
            v = hprev + dtTau * f;
        }
        // two-level LN reduction: SMEM then L2 atomics
        if (tid < 64) { sm[OFF_REDS + tid] = 0.f; sm[OFF_REDQ + tid] = 0.f; }
        __syncthreads();
        atomicAdd(&sm[OFF_REDS + r], v);
        atomicAdd(&sm[OFF_REDQ + r], v * v);
        __syncthreads();
        if (tid < 64) {
            atomicAdd(&g_rs[par * 64 + tid], sm[OFF_REDS + tid]);
            atomicAdd(&g_rq[par * 64 + tid], sm[OFF_REDQ + tid]);
        }
        bar_t += NCTA; grid_bar(bar_t);

        // ============ PHASE E: LayerNorm, h write, x prefetch ==============
        if (t + 1 < Tt) stage_issue(stA, x + (t + 1) * DIN, Tt * DIN, rs0, kk);
        {
            float s = __ldcg(&g_rs[par * 64 + r]);
            float q = __ldcg(&g_rq[par * 64 + r]);
            float mu   = s * (1.f / 512.f);
            float var  = q * (1.f / 512.f) - mu * mu;
            float rstd = rsqrtf(var + EPSc);
            float hn = (v - mu) * rstd * sm[OFF_B + 20 + cc] + sm[OFF_B + 24 + cc];
            hprev = hn;
            out[(size_t)r * (Tt * Hh) + (size_t)t * Hh + col] = hn;
            g_h[r * Hh + col] = hn;
        }
        if (tid < 64) {
            g_rs[(par ^ 1) * 64 + tid] = 0.f;
            g_rq[(par ^ 1) * 64 + tid] = 0.f;
        }
        bar_t += NCTA; grid_bar(bar_t);
    }
}

extern "C" void kernel_launch(void* const* d_in, const int* in_sizes, int n_in,
                              void* d_out, int out_size) {
    const float* x     = (const float*)d_in[0];
    const float* Wm    = (const float*)d_in[1];
    const float* bm    = (const float*)d_in[2];
    const float* Wf1   = (const float*)d_in[3];
    const float* bf1   = (const float*)d_in[4];
    const float* Wf2   = (const float*)d_in[5];
    const float* bf2   = (const float*)d_in[6];
    const float* Wt    = (const float*)d_in[7];
    const float* bt    = (const float*)d_in[8];
    const float* gamma = (const float*)d_in[9];
    const float* beta  = (const float*)d_in[10];
    float* out = (float*)d_out;

    cudaFuncSetAttribute(ctlnn_main, cudaFuncAttributeMaxDynamicSharedMemorySize,
                         SMEM_FLOATS * sizeof(float));

    ctlnn_reset<<<64, 256>>>();
    ctlnn_main<<<NCTA, NTHR, SMEM_FLOATS * sizeof(float)>>>(
        x, Wm, bm, Wf1, bf1, Wf2, bf2, Wt, bt, gamma, beta, out);
}

// round 5
// speedup vs baseline: 2.2659x; 1.4045x over previous
#include <cuda_runtime.h>
#include <cmath>

// ---------------------------------------------------------------------------
// CTLNN persistent kernel, round 5.
// 128 CTAs x 256 threads. Column-partitioned fp32 weights in SMEM.
// Thread (kpart, r) computes ALL 4 CTA columns over a K/4 slice (4x SMEM
// activation reuse), SMEM K-reduction, 64 row-owner threads do nonlinearities
// and hold the recurrence state (hprev, dtTau) in registers.
// All activation exchange through L2 in fp32 (bf16 was 1.4e-3 rel_err: too
// lossy). cp.async double-buffered staging, FFMA2 inner loops, 4 grid
// barriers per step.
// ---------------------------------------------------------------------------

namespace {
constexpr int Bz   = 64;
constexpr int Tt   = 1024;
constexpr int DIN  = 256;
constexpr int Hh   = 512;
constexpr int NCTA = 128;
constexpr int NTHR = 256;
constexpr float DTc  = 0.01f;
constexpr float EPSc = 1e-5f;

// SMEM float offsets
constexpr int OFF_WM    = 0;       // 8*768  [c8][k] (4 g cols then 4 core cols)
constexpr int OFF_WT    = 6144;    // 4*512  [c][k]
constexpr int OFF_WF1   = 8192;
constexpr int OFF_WF2   = 10240;
constexpr int OFF_STAGE = 12288;   // 2 buffers * 4096 float4 (64KB each)
constexpr int OFF_RED   = 45056;   // 256 threads * 8 floats
constexpr int OFF_B     = 47104;   // 28 floats of biases/gamma/beta
constexpr int SMEM_FLOATS = 47136; // ~188.5 KB
}

// Cross-CTA state (device globals: no allocation allowed)
__device__ unsigned g_bar;
__device__ float g_rs[128], g_rq[128];
__device__ float g_h[Bz * Hh];
__device__ float g_core[Bz * Hh];
__device__ float g_z[Bz * Hh];
__device__ float g_a1[Bz * Hh];

__global__ void ctlnn_reset() {
    int i = blockIdx.x * blockDim.x + threadIdx.x;
    if (i == 0) g_bar = 0u;
    if (i < 128) { g_rs[i] = 0.f; g_rq[i] = 0.f; }
    for (int k = i; k < Bz * Hh; k += gridDim.x * blockDim.x) g_h[k] = 0.f;
}

// ---- helpers --------------------------------------------------------------
__device__ __forceinline__ void cp16(float4* dst, const void* src) {
    unsigned s = (unsigned)__cvta_generic_to_shared(dst);
    asm volatile("cp.async.cg.shared.global [%0], [%1], 16;" :: "r"(s), "l"(src));
}
__device__ __forceinline__ void cp_commit() {
    asm volatile("cp.async.commit_group;" ::: "memory");
}
template <int N>
__device__ __forceinline__ void cp_wait() {
    asm volatile("cp.async.wait_group %0;" :: "n"(N) : "memory");
}
__device__ __forceinline__ void fma2(unsigned long long& d,
                                     unsigned long long a, unsigned long long b) {
    asm volatile("fma.rn.f32x2 %0, %1, %2, %3;" : "=l"(d) : "l"(a), "l"(b), "l"(d));
}
__device__ __forceinline__ float hsum(unsigned long long u) {
    float lo, hi;
    asm("mov.b64 {%0,%1}, %2;" : "=f"(lo), "=f"(hi) : "l"(u));
    return lo + hi;
}

__device__ __forceinline__ void grid_bar(unsigned target) {
    __threadfence();
    __syncthreads();
    if (threadIdx.x == 0) {
        atomicAdd(&g_bar, 1u);
        unsigned v;
        do {
            asm volatile("ld.global.acquire.gpu.u32 %0, [%1];"
                         : "=r"(v) : "l"(&g_bar));
        } while (v < target);
    }
    __syncthreads();
}

// Stage one 64-row x 64-granule(16B) chunk into SMEM with XOR swizzle.
__device__ __forceinline__ void stage_chunk(float4* __restrict__ dst,
                                            const char* __restrict__ gbase,
                                            size_t rstrideB, int rs0, int kk) {
#pragma unroll
    for (int i = 0; i < 16; ++i) {
        int rs = rs0 + i * 4;
        cp16(dst + rs * 64 + (kk ^ (rs & 7)),
             gbase + (size_t)rs * rstrideB + kk * 16);
    }
    cp_commit();
}

// Phase-A chunk dot: 8 outputs (4 g + 4 core) over this thread's 16 granules.
__device__ __forceinline__ void dotA_chunk(const ulonglong2* __restrict__ st,
                                           int r, int sw, int kpart,
                                           const ulonglong2* __restrict__ wm,
                                           int ch64,
                                           unsigned long long ag[4][2],
                                           unsigned long long ac[4][2]) {
    const ulonglong2* sp = st + r * 64;
#pragma unroll 8
    for (int j = 0; j < 16; ++j) {
        int gi = kpart * 16 + j;
        ulonglong2 a = sp[gi ^ sw];
#pragma unroll
        for (int c = 0; c < 4; ++c) {
            ulonglong2 wg = wm[c * 192 + ch64 + gi];
            ulonglong2 wc = wm[(c + 4) * 192 + ch64 + gi];
            fma2(ag[c][0], a.x, wg.x); fma2(ag[c][1], a.y, wg.y);
            fma2(ac[c][0], a.x, wc.x); fma2(ac[c][1], a.y, wc.y);
        }
    }
}

// Generic chunk dot: 4 outputs over this thread's 16 granules of a 64-granule
// chunk; weight column stride 128 granules (K=512 fp32).
__device__ __forceinline__ void dot4_chunk(const ulonglong2* __restrict__ st,
                                           int r, int sw, int kpart,
                                           const ulonglong2* __restrict__ w,
                                           int ch64,
                                           unsigned long long acc[4][2]) {
    const ulonglong2* sp = st + r * 64;
#pragma unroll 8
    for (int j = 0; j < 16; ++j) {
        int gi = kpart * 16 + j;
        ulonglong2 a = sp[gi ^ sw];
#pragma unroll
        for (int c = 0; c < 4; ++c) {
            ulonglong2 ww = w[c * 128 + ch64 + gi];
            fma2(acc[c][0], a.x, ww.x);
            fma2(acc[c][1], a.y, ww.y);
        }
    }
}

__global__ void __launch_bounds__(NTHR, 1)
ctlnn_main(const float* __restrict__ x,
           const float* __restrict__ Wm,  const float* __restrict__ bm,
           const float* __restrict__ Wf1, const float* __restrict__ bf1,
           const float* __restrict__ Wf2, const float* __restrict__ bf2,
           const float* __restrict__ Wt,  const float* __restrict__ bt,
           const float* __restrict__ gamma, const float* __restrict__ beta,
           float* __restrict__ out) {
    extern __shared__ __align__(16) float sm[];
    const int tid = threadIdx.x;
    const int bid = blockIdx.x;

    // ---- one-time weight slice load ----
    for (int idx = tid; idx < 8 * 768; idx += NTHR) {
        int c8 = idx / 768;
        int k  = idx - c8 * 768;
        int srccol = (c8 < 4) ? (bid * 4 + c8) : (512 + bid * 4 + (c8 - 4));
        sm[OFF_WM + idx] = Wm[k * 1024 + srccol];
    }
    for (int idx = tid; idx < 4 * 512; idx += NTHR) {
        int c4 = idx >> 9;
        int k  = idx & 511;
        int col0 = bid * 4 + c4;
        sm[OFF_WT  + idx] = Wt [k * 512 + col0];
        sm[OFF_WF1 + idx] = Wf1[k * 512 + col0];
        sm[OFF_WF2 + idx] = Wf2[k * 512 + col0];
    }
    if (tid < 4) {
        int col0 = bid * 4 + tid;
        sm[OFF_B +  0 + tid] = bm[col0];
        sm[OFF_B +  4 + tid] = bm[512 + col0];
        sm[OFF_B +  8 + tid] = bt[col0];
        sm[OFF_B + 12 + tid] = bf1[col0];
        sm[OFF_B + 16 + tid] = bf2[col0];
        sm[OFF_B + 20 + tid] = gamma[col0];
        sm[OFF_B + 24 + tid] = beta[col0];
    }
    __syncthreads();

    float4* bufA = reinterpret_cast<float4*>(sm + OFF_STAGE);
    float4* bufB = bufA + 64 * 64;
    float4* redF4 = reinterpret_cast<float4*>(sm + OFF_RED);
    const ulonglong2* WmU  = reinterpret_cast<const ulonglong2*>(sm + OFF_WM);
    const ulonglong2* WtU  = reinterpret_cast<const ulonglong2*>(sm + OFF_WT);
    const ulonglong2* Wf1U = reinterpret_cast<const ulonglong2*>(sm + OFF_WF1);
    const ulonglong2* Wf2U = reinterpret_cast<const ulonglong2*>(sm + OFF_WF2);

    const int r     = tid & 63;       // batch row
    const int kpart = tid >> 6;       // K-quarter
    const int sw    = r & 7;
    const int rs0   = tid >> 6;       // staging row phase
    const int kk    = tid & 63;       // staging granule
    const int cbase = bid * 4;        // first owned column
    const bool owner = (kpart == 0);

    float4 hprev = make_float4(0.f, 0.f, 0.f, 0.f);
    float dtTau[4] = {0.f, 0.f, 0.f, 0.f};
    float vkeep[4] = {0.f, 0.f, 0.f, 0.f};

    unsigned bar_t = 0;

    // prefetch x(t=0) into bufA (1 group pending entering the loop)
    stage_chunk(bufA, (const char*)x, (size_t)Tt * DIN * 4, rs0, kk);

    for (int t = 0; t < Tt; ++t) {
        const int par = t & 1;

        // ============ PHASE A: mapped = [x_t, h] @ Wm ======================
        unsigned long long ag[4][2] = {}, ac[4][2] = {};
        stage_chunk(bufB, (const char*)g_h, Hh * 4, rs0, kk);        // h0 -> B
        cp_wait<1>(); __syncthreads();                               // x ready
        dotA_chunk(reinterpret_cast<const ulonglong2*>(bufA), r, sw, kpart,
                   WmU, 0, ag, ac);
        __syncthreads();
        stage_chunk(bufA, (const char*)g_h + 1024, Hh * 4, rs0, kk); // h1 -> A
        cp_wait<1>(); __syncthreads();                               // h0 ready
        dotA_chunk(reinterpret_cast<const ulonglong2*>(bufB), r, sw, kpart,
                   WmU, 64, ag, ac);
        cp_wait<0>(); __syncthreads();                               // h1 ready
        dotA_chunk(reinterpret_cast<const ulonglong2*>(bufA), r, sw, kpart,
                   WmU, 128, ag, ac);
        redF4[tid * 2 + 0] = make_float4(hsum(ag[0][0]) + hsum(ag[0][1]),
                                         hsum(ag[1][0]) + hsum(ag[1][1]),
                                         hsum(ag[2][0]) + hsum(ag[2][1]),
                                         hsum(ag[3][0]) + hsum(ag[3][1]));
        redF4[tid * 2 + 1] = make_float4(hsum(ac[0][0]) + hsum(ac[0][1]),
                                         hsum(ac[1][0]) + hsum(ac[1][1]),
                                         hsum(ac[2][0]) + hsum(ac[2][1]),
                                         hsum(ac[3][0]) + hsum(ac[3][1]));
        __syncthreads();
        if (owner) {
            float G[4] = {0, 0, 0, 0}, C[4] = {0, 0, 0, 0};
#pragma unroll
            for (int kp = 0; kp < 4; ++kp) {
                float4 pg = redF4[(kp * 64 + r) * 2 + 0];
                float4 pc = redF4[(kp * 64 + r) * 2 + 1];
                G[0] += pg.x; G[1] += pg.y; G[2] += pg.z; G[3] += pg.w;
                C[0] += pc.x; C[1] += pc.y; C[2] += pc.z; C[3] += pc.w;
            }
            float4 zf, cf;
            float* zp = &zf.x;
            float* cpp = &cf.x;
#pragma unroll
            for (int c = 0; c < 4; ++c) {
                float gv = G[c] + sm[OFF_B + c];
                float cv = C[c] + sm[OFF_B + 4 + c];
                float sg = 1.f / (1.f + expf(-gv));
                cpp[c] = cv;
                zp[c]  = sg * tanhf(cv);
            }
            *reinterpret_cast<float4*>(&g_z[r * Hh + cbase])    = zf;
            *reinterpret_cast<float4*>(&g_core[r * Hh + cbase]) = cf;
        }
        bar_t += NCTA; grid_bar(bar_t);

        // ===== PHASE B: tau = softplus(core@Wt+bt); PHASE C: a1 ============
        stage_chunk(bufA, (const char*)g_core,        Hh * 4, rs0, kk);
        stage_chunk(bufB, (const char*)g_core + 1024, Hh * 4, rs0, kk);
        unsigned long long at[4][2] = {};
        cp_wait<1>(); __syncthreads();                               // core0
        dot4_chunk(reinterpret_cast<const ulonglong2*>(bufA), r, sw, kpart,
                   WtU, 0, at);
        __syncthreads();
        stage_chunk(bufA, (const char*)g_z, Hh * 4, rs0, kk);        // z0 -> A
        cp_wait<1>(); __syncthreads();                               // core1
        dot4_chunk(reinterpret_cast<const ulonglong2*>(bufB), r, sw, kpart,
                   WtU, 64, at);
        redF4[tid * 2] = make_float4(hsum(at[0][0]) + hsum(at[0][1]),
                                     hsum(at[1][0]) + hsum(at[1][1]),
                                     hsum(at[2][0]) + hsum(at[2][1]),
                                     hsum(at[3][0]) + hsum(at[3][1]));
        __syncthreads();
        stage_chunk(bufB, (const char*)g_z + 1024, Hh * 4, rs0, kk); // z1 -> B
        if (owner) {
            float Tq[4] = {0, 0, 0, 0};
#pragma unroll
            for (int kp = 0; kp < 4; ++kp) {
                float4 p = redF4[(kp * 64 + r) * 2];
                Tq[0] += p.x; Tq[1] += p.y; Tq[2] += p.z; Tq[3] += p.w;
            }
#pragma unroll
            for (int c = 0; c < 4; ++c) {
                float tl = Tq[c] + sm[OFF_B + 8 + c];
                float spv = (tl > 20.f) ? tl : log1pf(expf(tl));
                dtTau[c] = DTc / (spv + 1e-6f);
            }
        }
        unsigned long long af[4][2] = {};
        cp_wait<1>(); __syncthreads();                               // z0 ready
        dot4_chunk(reinterpret_cast<const ulonglong2*>(bufA), r, sw, kpart,
                   Wf1U, 0, af);
        cp_wait<0>(); __syncthreads();                               // z1 ready
        dot4_chunk(reinterpret_cast<const ulonglong2*>(bufB), r, sw, kpart,
                   Wf1U, 64, af);
        redF4[tid * 2] = make_float4(hsum(af[0][0]) + hsum(af[0][1]),
                                     hsum(af[1][0]) + hsum(af[1][1]),
                                     hsum(af[2][0]) + hsum(af[2][1]),
                                     hsum(af[3][0]) + hsum(af[3][1]));
        __syncthreads();
        if (owner) {
            float F[4] = {0, 0, 0, 0};
#pragma unroll
            for (int kp = 0; kp < 4; ++kp) {
                float4 p = redF4[(kp * 64 + r) * 2];
                F[0] += p.x; F[1] += p.y; F[2] += p.z; F[3] += p.w;
            }
            float4 a1v;
            float* ap = &a1v.x;
#pragma unroll
            for (int c = 0; c < 4; ++c) {
                float f1 = F[c] + sm[OFF_B + 12 + c];
                ap[c] = f1 / (1.f + expf(-f1));
            }
            *reinterpret_cast<float4*>(&g_a1[r * Hh + cbase]) = a1v;
        }
        bar_t += NCTA; grid_bar(bar_t);

        // ===== PHASE D: f = a1@Wf2 + bf2; v = h + dt/tau * f ===============
        stage_chunk(bufA, (const char*)g_a1,        Hh * 4, rs0, kk);
        stage_chunk(bufB, (const char*)g_a1 + 1024, Hh * 4, rs0, kk);
        unsigned long long ao[4][2] = {};
        cp_wait<1>(); __syncthreads();                               // a1_0
        dot4_chunk(reinterpret_cast<const ulonglong2*>(bufA), r, sw, kpart,
                   Wf2U, 0, ao);
        __syncthreads();
        if (t + 1 < Tt) {                                            // x(t+1)->A
            stage_chunk(bufA, (const char*)(x + (size_t)(t + 1) * DIN),
                        (size_t)Tt * DIN * 4, rs0, kk);
            cp_wait<1>();
        } else {
            cp_wait<0>();
        }
        __syncthreads();                                             // a1_1
        dot4_chunk(reinterpret_cast<const ulonglong2*>(bufB), r, sw, kpart,
                   Wf2U, 64, ao);
        redF4[tid * 2] = make_float4(hsum(ao[0][0]) + hsum(ao[0][1]),
                                     hsum(ao[1][0]) + hsum(ao[1][1]),
                                     hsum(ao[2][0]) + hsum(ao[2][1]),
                                     hsum(ao[3][0]) + hsum(ao[3][1]));
        __syncthreads();
        if (owner) {
            float F[4] = {0, 0, 0, 0};
#pragma unroll
            for (int kp = 0; kp < 4; ++kp) {
                float4 p = redF4[(kp * 64 + r) * 2];
                F[0] += p.x; F[1] += p.y; F[2] += p.z; F[3] += p.w;
            }
            float s = 0.f, q = 0.f;
#pragma unroll
            for (int c = 0; c < 4; ++c) {
                float f = F[c] + sm[OFF_B + 16 + c];
                float hc = (c == 0) ? hprev.x : (c == 1) ? hprev.y
                         : (c == 2) ? hprev.z : hprev.w;
                float v = hc + dtTau[c] * f;
                vkeep[c] = v;
                s += v; q += v * v;
            }
            atomicAdd(&g_rs[par * 64 + r], s);
            atomicAdd(&g_rq[par * 64 + r], q);
        }
        bar_t += NCTA; grid_bar(bar_t);

        // ===== PHASE E: LayerNorm, publish h ===============================
        if (owner) {
            float s = __ldcg(&g_rs[par * 64 + r]);
            float q = __ldcg(&g_rq[par * 64 + r]);
            float mu   = s * (1.f / 512.f);
            float var  = q * (1.f / 512.f) - mu * mu;
            float rstd = rsqrtf(var + EPSc);
            float4 hn;
            hn.x = (vkeep[0] - mu) * rstd * sm[OFF_B + 20] + sm[OFF_B + 24];
            hn.y = (vkeep[1] - mu) * rstd * sm[OFF_B + 21] + sm[OFF_B + 25];
            hn.z = (vkeep[2] - mu) * rstd * sm[OFF_B + 22] + sm[OFF_B + 26];
            hn.w = (vkeep[3] - mu) * rstd * sm[OFF_B + 23] + sm[OFF_B + 27];
            hprev = hn;
            *reinterpret_cast<float4*>(out + (size_t)(r * Tt + t) * Hh + cbase) = hn;
            *reinterpret_cast<float4*>(&g_h[r * Hh + cbase]) = hn;
        } else if (tid >= 64 && tid < 192) {
            int i = tid - 64;  // 0..127: first 64 -> rs, next 64 -> rq
            if (i < 64) g_rs[(par ^ 1) * 64 + i] = 0.f;
            else        g_rq[(par ^ 1) * 64 + (i - 64)] = 0.f;
        }
        bar_t += NCTA; grid_bar(bar_t);
    }
}

extern "C" void kernel_launch(void* const* d_in, const int* in_sizes, int n_in,
                              void* d_out, int out_size) {
    const float* x     = (const float*)d_in[0];
    const float* Wm    = (const float*)d_in[1];
    const float* bm    = (const float*)d_in[2];
    const float* Wf1   = (const float*)d_in[3];
    const float* bf1   = (const float*)d_in[4];
    const float* Wf2   = (const float*)d_in[5];
    const float* bf2   = (const float*)d_in[6];
    const float* Wt    = (const float*)d_in[7];
    const float* bt    = (const float*)d_in[8];
    const float* gamma = (const float*)d_in[9];
    const float* beta  = (const float*)d_in[10];
    float* out = (float*)d_out;

    cudaFuncSetAttribute(ctlnn_main, cudaFuncAttributeMaxDynamicSharedMemorySize,
                         SMEM_FLOATS * sizeof(float));

    ctlnn_reset<<<64, 256>>>();
    ctlnn_main<<<NCTA, NTHR, SMEM_FLOATS * sizeof(float)>>>(
        x, Wm, bm, Wf1, bf1, Wf2, bf2, Wt, bt, gamma, beta, out);
}

// round 6
// speedup vs baseline: 2.4481x; 1.0804x over previous
#include <cuda_runtime.h>
#include <cmath>

// ---------------------------------------------------------------------------
// CTLNN persistent kernel, round 6.
// 128 CTAs x 512 threads (16 warps). Column-partitioned fp32 weights in SMEM.
// Thread (kpart in 0..7, r in 0..63) computes all 4 CTA columns over a K/8
// interleaved slice. LayerNorm folded into phase A: gamma pre-multiplied into
// Wm's h-rows, per-row rstd folded into staged activations, beta/mu constants
// added by owners => raw v exchanged, only 3 grid barriers per step.
// cp.async double-buffered staging, FFMA2 inner loops.
// ---------------------------------------------------------------------------

namespace {
constexpr int Bz   = 64;
constexpr int Tt   = 1024;
constexpr int DIN  = 256;
constexpr int Hh   = 512;
constexpr int NCTA = 128;
constexpr int NTHR = 512;
constexpr float DTc  = 0.01f;
constexpr float EPSc = 1e-5f;

// SMEM float offsets
constexpr int OFF_WMX   = 0;        // 8 cols x 256 (x-rows of Wm)        2048
constexpr int OFF_WMV   = 2048;     // 8 cols x 512 (h-rows, gamma-folded) 4096
constexpr int OFF_WT    = 6144;     // 4 x 512
constexpr int OFF_WF1   = 8192;
constexpr int OFF_WF2   = 10240;
constexpr int OFF_STAGE = 12288;    // 2 buffers x 4096 float4 = 32768 floats
constexpr int OFF_RED   = 45056;    // 512 threads x 8 floats
constexpr int OFF_B     = 49152;    // 44 consts (see below)
constexpr int OFF_RSTD  = 49200;    // 64
constexpr int SMEM_FLOATS = 49264;  // ~197 KB
// OFF_B: [0..3] bm_g [4..7] bm_core [8..11] bt [12..15] bf1 [16..19] bf2
//        [20..23] gamma_c [24..27] beta_c [28..35] Bsum (8 cols) [36..43] Gsum
}

// Cross-CTA state (device globals: no allocation allowed)
__device__ unsigned g_bar;
__device__ float g_rs[128], g_rq[128];
__device__ float g_v[Bz * Hh];
__device__ float g_core[Bz * Hh];
__device__ float g_z[Bz * Hh];
__device__ float g_a1[Bz * Hh];

__global__ void ctlnn_reset() {
    int i = blockIdx.x * blockDim.x + threadIdx.x;
    if (i == 0) g_bar = 0u;
    if (i < 128) { g_rs[i] = 0.f; g_rq[i] = 0.f; }
    for (int k = i; k < Bz * Hh; k += gridDim.x * blockDim.x) g_v[k] = 0.f;
}

// ---- helpers --------------------------------------------------------------
__device__ __forceinline__ void cp16(float4* dst, const void* src) {
    unsigned s = (unsigned)__cvta_generic_to_shared(dst);
    asm volatile("cp.async.cg.shared.global [%0], [%1], 16;" :: "r"(s), "l"(src));
}
__device__ __forceinline__ void cp_commit() {
    asm volatile("cp.async.commit_group;" ::: "memory");
}
template <int N>
__device__ __forceinline__ void cp_wait() {
    asm volatile("cp.async.wait_group %0;" :: "n"(N) : "memory");
}
__device__ __forceinline__ void fma2(unsigned long long& d,
                                     unsigned long long a, unsigned long long b) {
    asm volatile("fma.rn.f32x2 %0, %1, %2, %3;" : "=l"(d) : "l"(a), "l"(b), "l"(d));
}
__device__ __forceinline__ unsigned long long mul2(unsigned long long a,
                                                   unsigned long long b) {
    unsigned long long d;
    asm("mul.rn.f32x2 %0, %1, %2;" : "=l"(d) : "l"(a), "l"(b));
    return d;
}
__device__ __forceinline__ float hsum(unsigned long long u) {
    float lo, hi;
    asm("mov.b64 {%0,%1}, %2;" : "=f"(lo), "=f"(hi) : "l"(u));
    return lo + hi;
}

__device__ __forceinline__ void grid_bar(unsigned target) {
    __threadfence();
    __syncthreads();
    if (threadIdx.x == 0) {
        atomicAdd(&g_bar, 1u);
        unsigned v;
        do {
            asm volatile("ld.global.acquire.gpu.u32 %0, [%1];"
                         : "=r"(v) : "l"(&g_bar));
        } while (v < target);
    }
    __syncthreads();
}

// Stage one 64-row x 64-granule(16B) chunk into SMEM with XOR swizzle.
__device__ __forceinline__ void stage_chunk(float4* __restrict__ dst,
                                            const char* __restrict__ gbase,
                                            size_t rstrideB, int rs0, int kk) {
#pragma unroll
    for (int i = 0; i < 8; ++i) {
        int rs = rs0 + i * 8;
        cp16(dst + rs * 64 + (kk ^ (rs & 7)),
             gbase + (size_t)rs * rstrideB + kk * 16);
    }
    cp_commit();
}

// 8-output chunk dot (phase A): granules l = j*8+kpart of a 64-granule chunk.
template <bool SCALE>
__device__ __forceinline__ void dot8(const ulonglong2* __restrict__ sp, int sw,
                                     int kpart,
                                     const ulonglong2* __restrict__ wbase,
                                     int wstride, int goff,
                                     unsigned long long scale2,
                                     unsigned long long ag[4][2],
                                     unsigned long long ac[4][2]) {
#pragma unroll
    for (int j = 0; j < 8; ++j) {
        int l = j * 8 + kpart;
        ulonglong2 a = sp[l ^ sw];
        if (SCALE) { a.x = mul2(a.x, scale2); a.y = mul2(a.y, scale2); }
        int wi = goff + l;
#pragma unroll
        for (int c = 0; c < 4; ++c) {
            ulonglong2 wg = wbase[c * wstride + wi];
            ulonglong2 wc = wbase[(4 + c) * wstride + wi];
            fma2(ag[c][0], a.x, wg.x); fma2(ag[c][1], a.y, wg.y);
            fma2(ac[c][0], a.x, wc.x); fma2(ac[c][1], a.y, wc.y);
        }
    }
}

// 4-output chunk dot (phases B/C/D).
__device__ __forceinline__ void dot4(const ulonglong2* __restrict__ sp, int sw,
                                     int kpart,
                                     const ulonglong2* __restrict__ w,
                                     int goff,
                                     unsigned long long acc[4][2]) {
#pragma unroll
    for (int j = 0; j < 8; ++j) {
        int l = j * 8 + kpart;
        ulonglong2 a = sp[l ^ sw];
        int wi = goff + l;
#pragma unroll
        for (int c = 0; c < 4; ++c) {
            ulonglong2 ww = w[c * 128 + wi];
            fma2(acc[c][0], a.x, ww.x);
            fma2(acc[c][1], a.y, ww.y);
        }
    }
}

__global__ void __launch_bounds__(NTHR, 1)
ctlnn_main(const float* __restrict__ x,
           const float* __restrict__ Wm,  const float* __restrict__ bm,
           const float* __restrict__ Wf1, const float* __restrict__ bf1,
           const float* __restrict__ Wf2, const float* __restrict__ bf2,
           const float* __restrict__ Wt,  const float* __restrict__ bt,
           const float* __restrict__ gamma, const float* __restrict__ beta,
           float* __restrict__ out) {
    extern __shared__ __align__(16) float sm[];
    const int tid = threadIdx.x;
    const int bid = blockIdx.x;

    // ---- one-time weight slice load ----
    for (int idx = tid; idx < 8 * 256; idx += NTHR) {          // Wm x-rows
        int c8 = idx >> 8;
        int k  = idx & 255;
        int srccol = (c8 < 4) ? (bid * 4 + c8) : (512 + bid * 4 + (c8 - 4));
        sm[OFF_WMX + idx] = Wm[k * 1024 + srccol];
    }
    for (int idx = tid; idx < 8 * 512; idx += NTHR) {          // Wm h-rows *gamma
        int c8 = idx >> 9;
        int k  = idx & 511;
        int srccol = (c8 < 4) ? (bid * 4 + c8) : (512 + bid * 4 + (c8 - 4));
        sm[OFF_WMV + idx] = Wm[(256 + k) * 1024 + srccol] * gamma[k];
    }
    for (int idx = tid; idx < 4 * 512; idx += NTHR) {
        int c4 = idx >> 9;
        int k  = idx & 511;
        int col0 = bid * 4 + c4;
        sm[OFF_WT  + idx] = Wt [k * 512 + col0];
        sm[OFF_WF1 + idx] = Wf1[k * 512 + col0];
        sm[OFF_WF2 + idx] = Wf2[k * 512 + col0];
    }
    if (tid < 4) {
        int col0 = bid * 4 + tid;
        sm[OFF_B +  0 + tid] = bm[col0];
        sm[OFF_B +  4 + tid] = bm[512 + col0];
        sm[OFF_B +  8 + tid] = bt[col0];
        sm[OFF_B + 12 + tid] = bf1[col0];
        sm[OFF_B + 16 + tid] = bf2[col0];
        sm[OFF_B + 20 + tid] = gamma[col0];
        sm[OFF_B + 24 + tid] = beta[col0];
    }
    // per-column LN constants: Bsum = sum_k beta_k*Wm_h[k,c], Gsum = sum gamma_k*Wm_h[k,c]
    {
        int w = tid >> 5, lane = tid & 31;
        if (w < 8) {
            int srccol = (w < 4) ? (bid * 4 + w) : (512 + bid * 4 + (w - 4));
            float sb = 0.f, sg = 0.f;
            for (int k = lane; k < 512; k += 32) {
                float wv = Wm[(256 + k) * 1024 + srccol];
                sb += beta[k] * wv;
                sg += gamma[k] * wv;
            }
#pragma unroll
            for (int o = 16; o; o >>= 1) {
                sb += __shfl_xor_sync(~0u, sb, o);
                sg += __shfl_xor_sync(~0u, sg, o);
            }
            if (lane == 0) { sm[OFF_B + 28 + w] = sb; sm[OFF_B + 36 + w] = sg; }
        }
    }
    __syncthreads();

    float4* bufA = reinterpret_cast<float4*>(sm + OFF_STAGE);
    float4* bufB = bufA + 64 * 64;
    float4* redF4 = reinterpret_cast<float4*>(sm + OFF_RED);
    const ulonglong2* WMXu = reinterpret_cast<const ulonglong2*>(sm + OFF_WMX);
    const ulonglong2* WMVu = reinterpret_cast<const ulonglong2*>(sm + OFF_WMV);
    const ulonglong2* WTu  = reinterpret_cast<const ulonglong2*>(sm + OFF_WT);
    const ulonglong2* WF1u = reinterpret_cast<const ulonglong2*>(sm + OFF_WF1);
    const ulonglong2* WF2u = reinterpret_cast<const ulonglong2*>(sm + OFF_WF2);

    const int r     = tid & 63;        // batch row
    const int kpart = tid >> 6;        // K-eighth (0..7)
    const int sw    = r & 7;
    const int rs0   = tid >> 6;        // staging row phase (0..7)
    const int kk    = tid & 63;        // staging granule
    const int cbase = bid * 4;
    const bool owner = (kpart == 0);   // tid < 64

    float4 hprev = make_float4(0.f, 0.f, 0.f, 0.f);
    float dtTau[4] = {0.f, 0.f, 0.f, 0.f};
    float vkeep[4] = {0.f, 0.f, 0.f, 0.f};

    unsigned bar_t = 0;

    // prefetch x(t=0) into bufA (1 group pending at loop entry)
    stage_chunk(bufA, (const char*)x, (size_t)Tt * DIN * 4, rs0, kk);

    for (int t = 0; t < Tt; ++t) {
        const int par = t & 1;

        // ============ PHASE A: mapped = [x_t, h] @ Wm  (LN folded) =========
        stage_chunk(bufB, (const char*)g_v, Hh * 4, rs0, kk);        // v0 -> B
        float muv = 0.f, rstdv = 0.f;
        if (owner) {
            if (t > 0) {   // finalize step t-1: LN of vkeep, write out
                int pp = (t - 1) & 1;
                float s = __ldcg(&g_rs[pp * 64 + r]);
                float q = __ldcg(&g_rq[pp * 64 + r]);
                muv = s * (1.f / 512.f);
                float var = q * (1.f / 512.f) - muv * muv;
                rstdv = rsqrtf(var + EPSc);
                float4 hn;
                hn.x = (vkeep[0] - muv) * rstdv * sm[OFF_B + 20] + sm[OFF_B + 24];
                hn.y = (vkeep[1] - muv) * rstdv * sm[OFF_B + 21] + sm[OFF_B + 25];
                hn.z = (vkeep[2] - muv) * rstdv * sm[OFF_B + 22] + sm[OFF_B + 26];
                hn.w = (vkeep[3] - muv) * rstdv * sm[OFF_B + 23] + sm[OFF_B + 27];
                *reinterpret_cast<float4*>(
                    out + (size_t)(r * Tt + (t - 1)) * Hh + cbase) = hn;
                hprev = hn;
            }
            sm[OFF_RSTD + r] = rstdv;   // 0 at t=0 -> v-dot contributes 0
        }
        unsigned long long ag[4][2] = {}, ac[4][2] = {};
        cp_wait<1>(); __syncthreads();                               // x ready
        dot8<false>(reinterpret_cast<const ulonglong2*>(bufA) + r * 64, sw,
                    kpart, WMXu, 64, 0, 0ull, ag, ac);
        __syncthreads();
        stage_chunk(bufA, (const char*)g_v + 1024, Hh * 4, rs0, kk); // v1 -> A
        unsigned long long rstd2;
        {
            float rv = sm[OFF_RSTD + r];
            asm("mov.b64 %0, {%1, %1};" : "=l"(rstd2) : "f"(rv));
        }
        cp_wait<1>(); __syncthreads();                               // v0 ready
        dot8<true>(reinterpret_cast<const ulonglong2*>(bufB) + r * 64, sw,
                   kpart, WMVu, 128, 0, rstd2, ag, ac);
        cp_wait<0>(); __syncthreads();                               // v1 ready
        dot8<true>(reinterpret_cast<const ulonglong2*>(bufA) + r * 64, sw,
                   kpart, WMVu, 128, 64, rstd2, ag, ac);
        redF4[tid * 2 + 0] = make_float4(hsum(ag[0][0]) + hsum(ag[0][1]),
                                         hsum(ag[1][0]) + hsum(ag[1][1]),
                                         hsum(ag[2][0]) + hsum(ag[2][1]),
                                         hsum(ag[3][0]) + hsum(ag[3][1]));
        redF4[tid * 2 + 1] = make_float4(hsum(ac[0][0]) + hsum(ac[0][1]),
                                         hsum(ac[1][0]) + hsum(ac[1][1]),
                                         hsum(ac[2][0]) + hsum(ac[2][1]),
                                         hsum(ac[3][0]) + hsum(ac[3][1]));
        __syncthreads();
        if (owner) {
            float G[4] = {0, 0, 0, 0}, C[4] = {0, 0, 0, 0};
#pragma unroll
            for (int kp = 0; kp < 8; ++kp) {
                float4 pg = redF4[(kp * 64 + r) * 2 + 0];
                float4 pc = redF4[(kp * 64 + r) * 2 + 1];
                G[0] += pg.x; G[1] += pg.y; G[2] += pg.z; G[3] += pg.w;
                C[0] += pc.x; C[1] += pc.y; C[2] += pc.z; C[3] += pc.w;
            }
            float4 zf, cf;
            float* zp = &zf.x;
            float* cpp = &cf.x;
            float mr = muv * rstdv;
#pragma unroll
            for (int c = 0; c < 4; ++c) {
                float gv = G[c] + sm[OFF_B + c];
                float cv = C[c] + sm[OFF_B + 4 + c];
                if (t > 0) {
                    gv += sm[OFF_B + 28 + c]     - mr * sm[OFF_B + 36 + c];
                    cv += sm[OFF_B + 28 + 4 + c] - mr * sm[OFF_B + 36 + 4 + c];
                }
                float sg = 1.f / (1.f + expf(-gv));
                cpp[c] = cv;
                zp[c]  = sg * tanhf(cv);
            }
            *reinterpret_cast<float4*>(&g_z[r * Hh + cbase])    = zf;
            *reinterpret_cast<float4*>(&g_core[r * Hh + cbase]) = cf;
        }
        bar_t += NCTA; grid_bar(bar_t);
        // zero the LN accumulators of parity (par^1) for reuse at step t+1
        if (bid == 0 && tid >= 64 && tid < 192) {
            int i = tid - 64;
            if (i < 64) g_rs[(par ^ 1) * 64 + i] = 0.f;
            else        g_rq[(par ^ 1) * 64 + (i - 64)] = 0.f;
        }

        // ===== PHASE B: tau; PHASE C: a1 = silu(z@Wf1+bf1) =================
        stage_chunk(bufA, (const char*)g_core,        Hh * 4, rs0, kk);
        stage_chunk(bufB, (const char*)g_core + 1024, Hh * 4, rs0, kk);
        unsigned long long at[4][2] = {};
        cp_wait<1>(); __syncthreads();                               // core0
        dot4(reinterpret_cast<const ulonglong2*>(bufA) + r * 64, sw, kpart,
             WTu, 0, at);
        __syncthreads();
        stage_chunk(bufA, (const char*)g_z, Hh * 4, rs0, kk);        // z0 -> A
        cp_wait<1>(); __syncthreads();                               // core1
        dot4(reinterpret_cast<const ulonglong2*>(bufB) + r * 64, sw, kpart,
             WTu, 64, at);
        redF4[tid * 2] = make_float4(hsum(at[0][0]) + hsum(at[0][1]),
                                     hsum(at[1][0]) + hsum(at[1][1]),
                                     hsum(at[2][0]) + hsum(at[2][1]),
                                     hsum(at[3][0]) + hsum(at[3][1]));
        __syncthreads();
        stage_chunk(bufB, (const char*)g_z + 1024, Hh * 4, rs0, kk); // z1 -> B
        if (owner) {
            float Tq[4] = {0, 0, 0, 0};
#pragma unroll
            for (int kp = 0; kp < 8; ++kp) {
                float4 p = redF4[(kp * 64 + r) * 2];
                Tq[0] += p.x; Tq[1] += p.y; Tq[2] += p.z; Tq[3] += p.w;
            }
#pragma unroll
            for (int c = 0; c < 4; ++c) {
                float tl = Tq[c] + sm[OFF_B + 8 + c];
                float spv = (tl > 20.f) ? tl : log1pf(expf(tl));
                dtTau[c] = DTc / (spv + 1e-6f);
            }
        }
        unsigned long long af[4][2] = {};
        cp_wait<1>(); __syncthreads();                               // z0 ready
        dot4(reinterpret_cast<const ulonglong2*>(bufA) + r * 64, sw, kpart,
             WF1u, 0, af);
        cp_wait<0>(); __syncthreads();                               // z1 ready
        dot4(reinterpret_cast<const ulonglong2*>(bufB) + r * 64, sw, kpart,
             WF1u, 64, af);
        redF4[tid * 2] = make_float4(hsum(af[0][0]) + hsum(af[0][1]),
                                     hsum(af[1][0]) + hsum(af[1][1]),
                                     hsum(af[2][0]) + hsum(af[2][1]),
                                     hsum(af[3][0]) + hsum(af[3][1]));
        __syncthreads();
        if (owner) {
            float F[4] = {0, 0, 0, 0};
#pragma unroll
            for (int kp = 0; kp < 8; ++kp) {
                float4 p = redF4[(kp * 64 + r) * 2];
                F[0] += p.x; F[1] += p.y; F[2] += p.z; F[3] += p.w;
            }
            float4 a1v;
            float* ap = &a1v.x;
#pragma unroll
            for (int c = 0; c < 4; ++c) {
                float f1 = F[c] + sm[OFF_B + 12 + c];
                ap[c] = f1 / (1.f + expf(-f1));
            }
            *reinterpret_cast<float4*>(&g_a1[r * Hh + cbase]) = a1v;
        }
        bar_t += NCTA; grid_bar(bar_t);

        // ===== PHASE D: f = a1@Wf2 + bf2; v = h + dt/tau * f ===============
        stage_chunk(bufA, (const char*)g_a1,        Hh * 4, rs0, kk);
        stage_chunk(bufB, (const char*)g_a1 + 1024, Hh * 4, rs0, kk);
        unsigned long long ao[4][2] = {};
        cp_wait<1>(); __syncthreads();                               // a1_0
        dot4(reinterpret_cast<const ulonglong2*>(bufA) + r * 64, sw, kpart,
             WF2u, 0, ao);
        __syncthreads();
        if (t + 1 < Tt) {                                            // x(t+1)->A
            stage_chunk(bufA, (const char*)(x + (size_t)(t + 1) * DIN),
                        (size_t)Tt * DIN * 4, rs0, kk);
            cp_wait<1>();
        } else {
            cp_wait<0>();
        }
        __syncthreads();                                             // a1_1
        dot4(reinterpret_cast<const ulonglong2*>(bufB) + r * 64, sw, kpart,
             WF2u, 64, ao);
        redF4[tid * 2] = make_float4(hsum(ao[0][0]) + hsum(ao[0][1]),
                                     hsum(ao[1][0]) + hsum(ao[1][1]),
                                     hsum(ao[2][0]) + hsum(ao[2][1]),
                                     hsum(ao[3][0]) + hsum(ao[3][1]));
        __syncthreads();
        if (owner) {
            float F[4] = {0, 0, 0, 0};
#pragma unroll
            for (int kp = 0; kp < 8; ++kp) {
                float4 p = redF4[(kp * 64 + r) * 2];
                F[0] += p.x; F[1] += p.y; F[2] += p.z; F[3] += p.w;
            }
            float s = 0.f, q = 0.f;
            float4 vv;
            float* vp = &vv.x;
#pragma unroll
            for (int c = 0; c < 4; ++c) {
                float f = F[c] + sm[OFF_B + 16 + c];
                float hc = (c == 0) ? hprev.x : (c == 1) ? hprev.y
                         : (c == 2) ? hprev.z : hprev.w;
                float v = hc + dtTau[c] * f;
                vkeep[c] = v;
                vp[c] = v;
                s += v; q += v * v;
            }
            *reinterpret_cast<float4*>(&g_v[r * Hh + cbase]) = vv;
            atomicAdd(&g_rs[par * 64 + r], s);
            atomicAdd(&g_rq[par * 64 + r], q);
        }
        bar_t += NCTA; grid_bar(bar_t);
    }

    // final output row (t = Tt-1)
    if (owner) {
        int pp = (Tt - 1) & 1;
        float s = __ldcg(&g_rs[pp * 64 + r]);
        float q = __ldcg(&g_rq[pp * 64 + r]);
        float muv = s * (1.f / 512.f);
        float var = q * (1.f / 512.f) - muv * muv;
        float rstdv = rsqrtf(var + EPSc);
        float4 hn;
        hn.x = (vkeep[0] - muv) * rstdv * sm[OFF_B + 20] + sm[OFF_B + 24];
        hn.y = (vkeep[1] - muv) * rstdv * sm[OFF_B + 21] + sm[OFF_B + 25];
        hn.z = (vkeep[2] - muv) * rstdv * sm[OFF_B + 22] + sm[OFF_B + 26];
        hn.w = (vkeep[3] - muv) * rstdv * sm[OFF_B + 23] + sm[OFF_B + 27];
        *reinterpret_cast<float4*>(
            out + (size_t)(r * Tt + (Tt - 1)) * Hh + cbase) = hn;
    }
}

extern "C" void kernel_launch(void* const* d_in, const int* in_sizes, int n_in,
                              void* d_out, int out_size) {
    const float* x     = (const float*)d_in[0];
    const float* Wm    = (const float*)d_in[1];
    const float* bm    = (const float*)d_in[2];
    const float* Wf1   = (const float*)d_in[3];
    const float* bf1   = (const float*)d_in[4];
    const float* Wf2   = (const float*)d_in[5];
    const float* bf2   = (const float*)d_in[6];
    const float* Wt    = (const float*)d_in[7];
    const float* bt    = (const float*)d_in[8];
    const float* gamma = (const float*)d_in[9];
    const float* beta  = (const float*)d_in[10];
    float* out = (float*)d_out;

    cudaFuncSetAttribute(ctlnn_main, cudaFuncAttributeMaxDynamicSharedMemorySize,
                         SMEM_FLOATS * sizeof(float));

    ctlnn_reset<<<64, 256>>>();
    ctlnn_main<<<NCTA, NTHR, SMEM_FLOATS * sizeof(float)>>>(
        x, Wm, bm, Wf1, bf1, Wf2, bf2, Wt, bt, gamma, beta, out);
}